// round 14
// baseline (speedup 1.0000x reference)
#include <cuda_runtime.h>
#include <cstdint>

#define B_ 8
#define N_ 10000
#define C_ 80
#define K_ 8
#define THR 0.5f
#define T2  0.99f            // collection threshold: ~100 candidates/class
#define NMS_NEG -1e9f
#define CAP 256
#define NBLK (B_ * C_)       // 640
#define TOT4 1600000         // B*N*C/4 float4 total

typedef unsigned long long u64;

// Scratch (allocation-free rule: __device__ globals; zero-initialized.
// INVARIANT: g_cand is all-zero at every launch start — collect writes the
// first cnt slots, nms_finish reads then re-zeroes ALL slots. Counters are
// reset by their reader. => graph-replay deterministic.)
__device__ u64    g_cand[NBLK * CAP];
__device__ int    g_ccnt[NBLK * 32];      // 128B stride per counter (atomics)
__device__ float  g_sel_score[NBLK * K_];
__device__ float4 g_sel_box  [NBLK * K_];
__device__ int    g_tick[B_ * 32];        // per-batch completion tickets

// key = (score_bits, N-n): max-key == (max score, lowest n). Valid scores are
// positive floats (uint order == float order); 0 = empty sentinel.
__device__ __forceinline__ u64 mkey(float v, int n) {
    return (((u64)__float_as_uint(v)) << 32) | (unsigned)(N_ - n);
}

__device__ __forceinline__ bool sup_iou(float4 a, float4 q) {
    float ih = fmaxf(fminf(a.z, q.z) - fmaxf(a.x, q.x), 0.0f);
    float iw = fmaxf(fminf(a.w, q.w) - fmaxf(a.y, q.y), 0.0f);
    float inter = ih * iw;
    float uni = (a.z - a.x) * (a.w - a.y) + (q.z - q.x) * (q.w - q.y) - inter;
    return inter / fmaxf(uni, 1e-9f) > 0.5f;
}

// ---------------------------------------------------------------------------
// Kernel 1: pure streaming collect. No smem, no sync, lean regs => full
// occupancy. Values > T2 append (score, n) keys to their (b,class) list.
// ---------------------------------------------------------------------------
__global__ __launch_bounds__(256) void collect(const float* __restrict__ scores)
{
    const float4* sp = reinterpret_cast<const float4*>(scores);
    const unsigned base = blockIdx.x * 1024u + threadIdx.x;
    #pragma unroll
    for (int k = 0; k < 4; k++) {
        unsigned idx4 = base + (k << 8);
        if (idx4 < TOT4) {
            float4 v = __ldg(sp + idx4);
            unsigned b  = idx4 / 200000u;            // batch
            unsigned r  = idx4 - b * 200000u;
            unsigned n  = r / 20u;                   // box row
            unsigned c0 = (r - n * 20u) << 2;        // class of v.x
            unsigned cb = b * C_ + c0;
            if (v.x > T2) { int p = atomicAdd(&g_ccnt[(cb  )*32], 1); if (p < CAP) g_cand[(cb  )*CAP+p] = mkey(v.x, (int)n); }
            if (v.y > T2) { int p = atomicAdd(&g_ccnt[(cb+1)*32], 1); if (p < CAP) g_cand[(cb+1)*CAP+p] = mkey(v.y, (int)n); }
            if (v.z > T2) { int p = atomicAdd(&g_ccnt[(cb+2)*32], 1); if (p < CAP) g_cand[(cb+2)*CAP+p] = mkey(v.z, (int)n); }
            if (v.w > T2) { int p = atomicAdd(&g_ccnt[(cb+3)*32], 1); if (p < CAP) g_cand[(cb+3)*CAP+p] = mkey(v.w, (int)n); }
        }
    }
}

// ---------------------------------------------------------------------------
// Kernel 2: 640 blocks x 32 threads (one warp, zero block barriers).
//  - keys loaded UNCONDITIONALLY (zero-sentinel slots; no cnt dependency),
//    then slots re-zeroed to keep the all-zero launch invariant;
//  - register greedy NMS (redux pops, batched box prefetch, warp-par IoU);
//  - per-batch ticket -> last finisher runs its batch's top-8 with ALL pops
//    first, then PARALLEL box loads + output writes (lane kx = rank kx).
// Output (f32): boxes[8][8][4] | scores[8][8] | classes[8][8] | valid[8]
// ---------------------------------------------------------------------------
__global__ __launch_bounds__(32) void nms_finish(
    const float* __restrict__ boxes, const float* __restrict__ scores,
    float* __restrict__ out)
{
    __shared__ float4 selbox[K_];
    __shared__ float  selsc[K_];
    __shared__ int    sel_n[K_];

    const int lane = threadIdx.x;
    const int blk  = blockIdx.x;
    const int b    = blk / C_;
    const int c    = blk % C_;

    const float4* bxp = reinterpret_cast<const float4*>(boxes) + (size_t)b * N_;

    // keys: unconditional load (overlaps the cnt load below), then re-zero
    u64 k[8];
    #pragma unroll
    for (int j = 0; j < 8; j++) k[j] = __ldg(&g_cand[blk * CAP + lane + (j << 5)]);
    int cnt = 0;
    if (lane == 0) { cnt = g_ccnt[blk * 32]; g_ccnt[blk * 32] = 0; }
    cnt = __shfl_sync(0xffffffffu, cnt, 0);
    #pragma unroll
    for (int j = 0; j < 8; j++) g_cand[blk * CAP + lane + (j << 5)] = 0ULL;
    const bool over = cnt > CAP;              // overflow -> exact fallback

    int  nsel = 0;
    bool exhausted = over;                    // skip candidate phase if over
    while (nsel < K_ && !exhausted) {
        float4 myb = make_float4(0.f, 0.f, 0.f, 0.f);
        float  mysc = 0.f;
        int    myn  = 0;
        int    npop = 0;
        for (int p = 0; p < 8; p++) {
            u64 g = k[0];
            #pragma unroll
            for (int j = 1; j < 8; j++) if (k[j] > g) g = k[j];
            unsigned hi = (unsigned)(g >> 32);
            unsigned bh = __reduce_max_sync(0xffffffffu, hi);
            if (bh == 0u) { exhausted = true; break; }
            unsigned lo = (hi == bh) ? (unsigned)g : 0u;
            unsigned bl = __reduce_max_sync(0xffffffffu, lo);
            u64 gbest = (((u64)bh) << 32) | bl;
            if (lane == p) {                       // record + prefetch box
                mysc = __uint_as_float(bh);
                myn  = N_ - (int)bl;
                myb  = __ldg(bxp + myn);
            }
            #pragma unroll
            for (int j = 0; j < 8; j++) if (k[j] == gbest) k[j] = 0;  // kill
            npop++;
        }

        for (int q = 0; q < npop && nsel < K_; q++) {
            float4 bb;
            bb.x = __shfl_sync(0xffffffffu, myb.x, q);
            bb.y = __shfl_sync(0xffffffffu, myb.y, q);
            bb.z = __shfl_sync(0xffffffffu, myb.z, q);
            bb.w = __shfl_sync(0xffffffffu, myb.w, q);
            float scq = __shfl_sync(0xffffffffu, mysc, q);
            int   nq  = __shfl_sync(0xffffffffu, myn, q);
            bool sup = (lane < nsel) ? sup_iou(bb, selbox[lane]) : false;
            if (!__ballot_sync(0xffffffffu, sup)) {
                if (lane == 0) {
                    selbox[nsel] = bb; selsc[nsel] = scq; sel_n[nsel] = nq;
                }
                nsel++;
                __syncwarp();
            }
        }
    }

    // ---- exact fallback (probability ~0 on this data) ----
    if (nsel < K_) {
        const float* scp = scores + (size_t)b * N_ * C_ + c;
        while (nsel < K_) {
            u64 best = 0;
            for (int n = lane; n < N_; n += 32) {
                float v = __ldg(scp + (size_t)n * C_);
                if (v > THR) {
                    bool excl = false;
                    for (int j = 0; j < nsel; j++) if (sel_n[j] == n) excl = true;
                    if (!excl) {
                        float4 bb = __ldg(bxp + n);
                        for (int j = 0; j < nsel; j++)
                            if (sup_iou(bb, selbox[j])) { excl = true; break; }
                    }
                    if (!excl) { u64 kk = mkey(v, n); if (kk > best) best = kk; }
                }
            }
            #pragma unroll
            for (int off = 16; off > 0; off >>= 1) {
                u64 ob = __shfl_down_sync(0xffffffffu, best, off);
                if (ob > best) best = ob;
            }
            best = __shfl_sync(0xffffffffu, best, 0);
            if ((unsigned)(best >> 32) == 0u) break;
            int nn = N_ - (int)(best & 0xffffffffu);
            if (lane == 0) {
                selbox[nsel] = __ldg(bxp + nn);
                selsc[nsel]  = __uint_as_float((unsigned)(best >> 32));
                sel_n[nsel]  = nn;
            }
            nsel++;
            __syncwarp();
        }
    }

    // ---- publish results for this (b,c) ----
    if (lane < K_) {
        int o = blk * K_ + lane;
        int v = (lane < nsel);
        g_sel_score[o] = v ? selsc[lane] : NMS_NEG;   // invalid -> NEG (< THR)
        float4 z = make_float4(0.f, 0.f, 0.f, 0.f);
        g_sel_box[o] = v ? selbox[lane] : z;
    }
    __threadfence();
    __syncwarp();
    int tick = 0;
    if (lane == 0) tick = atomicAdd(&g_tick[b * 32], 1);
    tick = __shfl_sync(0xffffffffu, tick, 0);
    if (tick != C_ - 1) return;           // not this batch's last finisher
    __threadfence();                      // acquire: all 80 blocks' g_sel

    // ======== per-batch top-8: ALL pops first, then parallel box IO ========
    {
        const int base = b * C_ * K_;
        // key = (score_bits, 2047-j): max == (max score, lowest flat index j)
        u64 kk[20];
        #pragma unroll
        for (int q = 0; q < 20; q++) {        // j = lane + 32q, coalesced
            int j = lane + (q << 5);
            float v = g_sel_score[base + j];
            kk[q] = (v > THR)
                  ? ((((u64)__float_as_uint(v)) << 32) | (unsigned)(2047 - j))
                  : 0ULL;
        }
        unsigned myhi = 0u, mylo = 0u;        // lane kx <- pop of rank kx
        int vcnt = 0;
        for (int kx = 0; kx < K_; kx++) {
            u64 g = kk[0];
            #pragma unroll
            for (int q = 1; q < 20; q++) if (kk[q] > g) g = kk[q];
            unsigned hi = (unsigned)(g >> 32);
            unsigned bh = __reduce_max_sync(0xffffffffu, hi);
            if (bh == 0u) break;
            unsigned lo = (hi == bh) ? (unsigned)g : 0u;
            unsigned bl = __reduce_max_sync(0xffffffffu, lo);
            u64 gbest = (((u64)bh) << 32) | bl;
            #pragma unroll
            for (int q = 0; q < 20; q++) if (kk[q] == gbest) kk[q] = 0;
            if (lane == kx) { myhi = bh; mylo = bl; }
            vcnt++;
        }
        // parallel epilogue: lane kx owns output rank kx
        if (lane < K_) {
            float4* ob = reinterpret_cast<float4*>(out + b * 32 + lane * 4);
            if (myhi != 0u) {
                int j = 2047 - (int)mylo;
                float4 bb = __ldg(&g_sel_box[base + j]);
                float4 w;
                w.x = fminf(fmaxf(bb.x, 0.f), 1.f);
                w.y = fminf(fmaxf(bb.y, 0.f), 1.f);
                w.z = fminf(fmaxf(bb.z, 0.f), 1.f);
                w.w = fminf(fmaxf(bb.w, 0.f), 1.f);
                *ob = w;
                out[B_ * 32 + b * 8 + lane] = __uint_as_float(myhi);
                out[B_ * 40 + b * 8 + lane] = (float)(j >> 3);   // class = j // K
            } else {
                *ob = make_float4(0.f, 0.f, 0.f, 0.f);
                out[B_ * 32 + b * 8 + lane] = 0.f;
                out[B_ * 40 + b * 8 + lane] = 0.f;
            }
        }
        if (lane == 0) {
            out[B_ * 48 + b] = (float)vcnt;
            g_tick[b * 32] = 0;           // self-clean (no later readers)
        }
    }
}

extern "C" void kernel_launch(void* const* d_in, const int* in_sizes, int n_in,
                              void* d_out, int out_size)
{
    const float* boxes  = (const float*)d_in[0];
    const float* scores = (const float*)d_in[1];
    if (n_in >= 2 && in_sizes[0] > in_sizes[1]) {   // defensive input order
        const float* t = boxes; boxes = scores; scores = t;
    }
    collect<<<(TOT4 + 1023) / 1024, 256>>>(scores);          // 1563 blocks
    nms_finish<<<NBLK, 32>>>(boxes, scores, (float*)d_out);
}

// round 15
// speedup vs baseline: 144.8271x; 144.8271x over previous
#include <cuda_runtime.h>
#include <cstdint>

#define B_ 8
#define N_ 10000
#define C_ 80
#define K_ 8
#define THR 0.5f
#define T2  0.99f            // collection threshold: ~100 candidates/class
#define NMS_NEG -1e9f
#define CAP 256
#define NBLK (B_ * C_)       // 640
#define TOT4 1600000         // B*N*C/4 float4 total

typedef unsigned long long u64;

// Scratch (allocation-free rule: __device__ globals; zero-initialized; every
// counter is reset by its reader within the launch => graph-replay
// deterministic. g_cand slots beyond cnt may be stale — masked by cnt.)
__device__ u64    g_cand[NBLK * CAP];
__device__ int    g_ccnt[NBLK * 32];      // 128B stride per counter (atomics)
__device__ float  g_sel_score[NBLK * K_];
__device__ float4 g_sel_box  [NBLK * K_];
__device__ int    g_tick[B_ * 32];        // per-batch completion tickets

// key = (score_bits, N-n): max-key == (max score, lowest n). Valid scores are
// positive floats (uint order == float order); 0 = empty sentinel.
__device__ __forceinline__ u64 mkey(float v, int n) {
    return (((u64)__float_as_uint(v)) << 32) | (unsigned)(N_ - n);
}

__device__ __forceinline__ bool sup_iou(float4 a, float4 q) {
    float ih = fmaxf(fminf(a.z, q.z) - fmaxf(a.x, q.x), 0.0f);
    float iw = fmaxf(fminf(a.w, q.w) - fmaxf(a.y, q.y), 0.0f);
    float inter = ih * iw;
    float uni = (a.z - a.x) * (a.w - a.y) + (q.z - q.x) * (q.w - q.y) - inter;
    return inter / fmaxf(uni, 1e-9f) > 0.5f;
}

// ---------------------------------------------------------------------------
// Kernel 1: pure streaming collect. No smem, no sync, lean regs => full
// occupancy. Values > T2 append (score, n) keys to their (b,class) list.
// ---------------------------------------------------------------------------
__global__ __launch_bounds__(256) void collect(const float* __restrict__ scores)
{
    const float4* sp = reinterpret_cast<const float4*>(scores);
    const unsigned base = blockIdx.x * 1024u + threadIdx.x;
    #pragma unroll
    for (int k = 0; k < 4; k++) {
        unsigned idx4 = base + (k << 8);
        if (idx4 < TOT4) {
            float4 v = __ldg(sp + idx4);
            unsigned b  = idx4 / 200000u;            // batch
            unsigned r  = idx4 - b * 200000u;
            unsigned n  = r / 20u;                   // box row
            unsigned c0 = (r - n * 20u) << 2;        // class of v.x
            unsigned cb = b * C_ + c0;
            if (v.x > T2) { int p = atomicAdd(&g_ccnt[(cb  )*32], 1); if (p < CAP) g_cand[(cb  )*CAP+p] = mkey(v.x, (int)n); }
            if (v.y > T2) { int p = atomicAdd(&g_ccnt[(cb+1)*32], 1); if (p < CAP) g_cand[(cb+1)*CAP+p] = mkey(v.y, (int)n); }
            if (v.z > T2) { int p = atomicAdd(&g_ccnt[(cb+2)*32], 1); if (p < CAP) g_cand[(cb+2)*CAP+p] = mkey(v.z, (int)n); }
            if (v.w > T2) { int p = atomicAdd(&g_ccnt[(cb+3)*32], 1); if (p < CAP) g_cand[(cb+3)*CAP+p] = mkey(v.w, (int)n); }
        }
    }
}

// ---------------------------------------------------------------------------
// Kernel 2: 640 blocks x 32 threads (one warp, zero block barriers).
//  - keys: MASKED load by cnt (R13-proven). nms_finish NEVER writes g_cand,
//    so __ldg is legal here (the R14 zeroing + __ldg was UB and the 135x bug);
//  - register greedy NMS (redux pops, batched box prefetch, warp-par IoU);
//  - per-batch ticket -> last finisher runs its batch's top-8: ALL pops into
//    per-lane regs first, then PARALLEL box loads (plain LDG) + output writes.
// Output (f32): boxes[8][8][4] | scores[8][8] | classes[8][8] | valid[8]
// ---------------------------------------------------------------------------
__global__ __launch_bounds__(32) void nms_finish(
    const float* __restrict__ boxes, const float* __restrict__ scores,
    float* __restrict__ out)
{
    __shared__ float4 selbox[K_];
    __shared__ float  selsc[K_];
    __shared__ int    sel_n[K_];

    const int lane = threadIdx.x;
    const int blk  = blockIdx.x;
    const int b    = blk / C_;
    const int c    = blk % C_;

    int cnt = 0;
    if (lane == 0) { cnt = g_ccnt[blk * 32]; g_ccnt[blk * 32] = 0; }  // self-clean
    cnt = __shfl_sync(0xffffffffu, cnt, 0);
    const int m = (cnt > CAP) ? 0 : cnt;      // overflow -> exact fallback

    const float4* bxp = reinterpret_cast<const float4*>(boxes) + (size_t)b * N_;

    u64 k[8];
    #pragma unroll
    for (int j = 0; j < 8; j++) {
        int idx = lane + (j << 5);
        k[j] = (idx < m) ? __ldg(&g_cand[blk * CAP + idx]) : 0ULL;
    }

    int  nsel = 0;
    bool exhausted = (m == 0);
    while (nsel < K_ && !exhausted) {
        float4 myb = make_float4(0.f, 0.f, 0.f, 0.f);
        float  mysc = 0.f;
        int    myn  = 0;
        int    npop = 0;
        for (int p = 0; p < 8; p++) {
            u64 g = k[0];
            #pragma unroll
            for (int j = 1; j < 8; j++) if (k[j] > g) g = k[j];
            unsigned hi = (unsigned)(g >> 32);
            unsigned bh = __reduce_max_sync(0xffffffffu, hi);
            if (bh == 0u) { exhausted = true; break; }
            unsigned lo = (hi == bh) ? (unsigned)g : 0u;
            unsigned bl = __reduce_max_sync(0xffffffffu, lo);
            u64 gbest = (((u64)bh) << 32) | bl;
            if (lane == p) {                       // record + prefetch box
                mysc = __uint_as_float(bh);
                myn  = N_ - (int)bl;
                myb  = __ldg(bxp + myn);
            }
            #pragma unroll
            for (int j = 0; j < 8; j++) if (k[j] == gbest) k[j] = 0;  // kill
            npop++;
        }

        for (int q = 0; q < npop && nsel < K_; q++) {
            float4 bb;
            bb.x = __shfl_sync(0xffffffffu, myb.x, q);
            bb.y = __shfl_sync(0xffffffffu, myb.y, q);
            bb.z = __shfl_sync(0xffffffffu, myb.z, q);
            bb.w = __shfl_sync(0xffffffffu, myb.w, q);
            float scq = __shfl_sync(0xffffffffu, mysc, q);
            int   nq  = __shfl_sync(0xffffffffu, myn, q);
            bool sup = (lane < nsel) ? sup_iou(bb, selbox[lane]) : false;
            if (!__ballot_sync(0xffffffffu, sup)) {
                if (lane == 0) {
                    selbox[nsel] = bb; selsc[nsel] = scq; sel_n[nsel] = nq;
                }
                nsel++;
                __syncwarp();
            }
        }
    }

    // ---- exact fallback (probability ~0 on this data) ----
    if (nsel < K_) {
        const float* scp = scores + (size_t)b * N_ * C_ + c;
        while (nsel < K_) {
            u64 best = 0;
            for (int n = lane; n < N_; n += 32) {
                float v = __ldg(scp + (size_t)n * C_);
                if (v > THR) {
                    bool excl = false;
                    for (int j = 0; j < nsel; j++) if (sel_n[j] == n) excl = true;
                    if (!excl) {
                        float4 bb = __ldg(bxp + n);
                        for (int j = 0; j < nsel; j++)
                            if (sup_iou(bb, selbox[j])) { excl = true; break; }
                    }
                    if (!excl) { u64 kk = mkey(v, n); if (kk > best) best = kk; }
                }
            }
            #pragma unroll
            for (int off = 16; off > 0; off >>= 1) {
                u64 ob = __shfl_down_sync(0xffffffffu, best, off);
                if (ob > best) best = ob;
            }
            best = __shfl_sync(0xffffffffu, best, 0);
            if ((unsigned)(best >> 32) == 0u) break;
            int nn = N_ - (int)(best & 0xffffffffu);
            if (lane == 0) {
                selbox[nsel] = __ldg(bxp + nn);
                selsc[nsel]  = __uint_as_float((unsigned)(best >> 32));
                sel_n[nsel]  = nn;
            }
            nsel++;
            __syncwarp();
        }
    }

    // ---- publish results for this (b,c) ----
    if (lane < K_) {
        int o = blk * K_ + lane;
        int v = (lane < nsel);
        g_sel_score[o] = v ? selsc[lane] : NMS_NEG;   // invalid -> NEG (< THR)
        float4 z = make_float4(0.f, 0.f, 0.f, 0.f);
        g_sel_box[o] = v ? selbox[lane] : z;
    }
    __threadfence();
    __syncwarp();
    int tick = 0;
    if (lane == 0) tick = atomicAdd(&g_tick[b * 32], 1);
    tick = __shfl_sync(0xffffffffu, tick, 0);
    if (tick != C_ - 1) return;           // not this batch's last finisher
    __threadfence();                      // acquire: all 80 blocks' g_sel

    // ======== per-batch top-8: ALL pops first, then parallel box IO ========
    {
        const int base = b * C_ * K_;
        // key = (score_bits, 2047-j): max == (max score, lowest flat index j)
        u64 kk[20];
        #pragma unroll
        for (int q = 0; q < 20; q++) {        // j = lane + 32q, coalesced
            int j = lane + (q << 5);
            float v = g_sel_score[base + j];  // plain load (kernel writes it)
            kk[q] = (v > THR)
                  ? ((((u64)__float_as_uint(v)) << 32) | (unsigned)(2047 - j))
                  : 0ULL;
        }
        unsigned myhi = 0u, mylo = 0u;        // lane kx <- pop of rank kx
        int vcnt = 0;
        for (int kx = 0; kx < K_; kx++) {
            u64 g = kk[0];
            #pragma unroll
            for (int q = 1; q < 20; q++) if (kk[q] > g) g = kk[q];
            unsigned hi = (unsigned)(g >> 32);
            unsigned bh = __reduce_max_sync(0xffffffffu, hi);
            if (bh == 0u) break;
            unsigned lo = (hi == bh) ? (unsigned)g : 0u;
            unsigned bl = __reduce_max_sync(0xffffffffu, lo);
            u64 gbest = (((u64)bh) << 32) | bl;
            #pragma unroll
            for (int q = 0; q < 20; q++) if (kk[q] == gbest) kk[q] = 0;
            if (lane == kx) { myhi = bh; mylo = bl; }
            vcnt++;
        }
        // parallel epilogue: lane kx owns output rank kx (plain loads!)
        if (lane < K_) {
            float4* ob = reinterpret_cast<float4*>(out + b * 32 + lane * 4);
            if (myhi != 0u) {
                int j = 2047 - (int)mylo;
                float4 bb = g_sel_box[base + j];   // plain load, NOT __ldg
                float4 w;
                w.x = fminf(fmaxf(bb.x, 0.f), 1.f);
                w.y = fminf(fmaxf(bb.y, 0.f), 1.f);
                w.z = fminf(fmaxf(bb.z, 0.f), 1.f);
                w.w = fminf(fmaxf(bb.w, 0.f), 1.f);
                *ob = w;
                out[B_ * 32 + b * 8 + lane] = __uint_as_float(myhi);
                out[B_ * 40 + b * 8 + lane] = (float)(j >> 3);   // class = j // K
            } else {
                *ob = make_float4(0.f, 0.f, 0.f, 0.f);
                out[B_ * 32 + b * 8 + lane] = 0.f;
                out[B_ * 40 + b * 8 + lane] = 0.f;
            }
        }
        if (lane == 0) {
            out[B_ * 48 + b] = (float)vcnt;
            g_tick[b * 32] = 0;           // self-clean (no later readers)
        }
    }
}

extern "C" void kernel_launch(void* const* d_in, const int* in_sizes, int n_in,
                              void* d_out, int out_size)
{
    const float* boxes  = (const float*)d_in[0];
    const float* scores = (const float*)d_in[1];
    if (n_in >= 2 && in_sizes[0] > in_sizes[1]) {   // defensive input order
        const float* t = boxes; boxes = scores; scores = t;
    }
    collect<<<(TOT4 + 1023) / 1024, 256>>>(scores);          // 1563 blocks
    nms_finish<<<NBLK, 32>>>(boxes, scores, (float*)d_out);
}